// round 9
// baseline (speedup 1.0000x reference)
#include <cuda_runtime.h>
#include <cuda_bf16.h>
#include <cuda_fp16.h>
#include <math_constants.h>
#include <cstdint>

// Problem dims
#define BB 4
#define SS 4096
#define DD 768
#define RR (BB*SS)        // 16384
#define FF 385            // rfft bins
// Layouts
#define SLOT    772
#define MROWS   2432
#define GS_ROWS 2440
#define K3      2304      // fold K (bf16 3-term)
#define KA3     1536      // stage-3 A row len (fp16 hi|lo)
#define KB3     768       // stage-3 B row len (fp16 hi)
#define KA5     1664      // stage-5 A row len (fp16 hi|lo)
#define KB5     832       // stage-5 B row len (fp16 hi)
#define TWROWS  896
#define SCALE5  (1.0f/4096.0f)
#define ISCALE5 4096.0f

// ---------------- scratch ----------------
__device__ __nv_bfloat16 d_TwS[TWROWS * K3];
__device__ __nv_bfloat16 d_Ws [3 * DD * K3];
__device__ __half        d_Gs [GS_ROWS * KA3];
__device__ __half        d_Xs [(size_t)RR * KB3];
__device__ float         d_XFt[(size_t)MROWS * RR];
__device__ __half        d_OFs[(size_t)RR * KA5];
__device__ __half        d_ITb[DD * KB5];

// ---------------- helpers ----------------
__device__ __forceinline__ uint32_t s2u(const void* p) {
    uint32_t a;
    asm("{ .reg .u64 t; cvta.to.shared.u64 t, %1; cvt.u32.u64 %0, t; }" : "=r"(a) : "l"(p));
    return a;
}
__device__ __forceinline__ uint32_t swz(uint32_t o) { return o ^ ((o >> 3) & 0x70); }
#define CP16(dst, src) asm volatile("cp.async.cg.shared.global [%0], [%1], 16;" :: "r"(dst), "l"(src))
#define CP_COMMIT()    asm volatile("cp.async.commit_group;" ::: "memory")
#define WG(n) asm volatile("cp.async.wait_group " #n ";" ::: "memory")

__device__ __forceinline__ uint32_t packh(__half a, __half b) {
    return (uint32_t)__half_as_ushort(a) | ((uint32_t)__half_as_ushort(b) << 16);
}
__device__ __forceinline__ uint32_t packsplit_h(float v0, float v1, uint32_t& lo) {
    __half h0 = __float2half(v0); __half l0 = __float2half(v0 - __half2float(h0));
    __half h1 = __float2half(v1); __half l1 = __float2half(v1 - __half2float(h1));
    lo = packh(l0, l1);
    return packh(h0, h1);
}
__device__ __forceinline__ void split2b(float v, __nv_bfloat16& h, __nv_bfloat16& l) {
    h = __float2bfloat16(v);
    l = __float2bfloat16(v - __bfloat162float(h));
}
__device__ __forceinline__ uint32_t packbf(__nv_bfloat16 a, __nv_bfloat16 b) {
    return (uint32_t)__bfloat16_as_ushort(a) | ((uint32_t)__bfloat16_as_ushort(b) << 16);
}
__device__ __forceinline__ uint32_t packsplit_b(float v0, float v1, uint32_t& lo) {
    __nv_bfloat16 h0, l0, h1, l1; split2b(v0, h0, l0); split2b(v1, h1, l1);
    lo = packbf(l0, l1);
    return packbf(h0, h1);
}

template <bool BF>
__device__ __forceinline__ void mma16816(float* d, const uint32_t* a, uint32_t b0, uint32_t b1) {
    if constexpr (BF)
        asm volatile(
            "mma.sync.aligned.m16n8k16.row.col.f32.bf16.bf16.f32 "
            "{%0,%1,%2,%3}, {%4,%5,%6,%7}, {%8,%9}, {%0,%1,%2,%3};"
            : "+f"(d[0]), "+f"(d[1]), "+f"(d[2]), "+f"(d[3])
            : "r"(a[0]), "r"(a[1]), "r"(a[2]), "r"(a[3]), "r"(b0), "r"(b1));
    else
        asm volatile(
            "mma.sync.aligned.m16n8k16.row.col.f32.f16.f16.f32 "
            "{%0,%1,%2,%3}, {%4,%5,%6,%7}, {%8,%9}, {%0,%1,%2,%3};"
            : "+f"(d[0]), "+f"(d[1]), "+f"(d[2]), "+f"(d[3])
            : "r"(a[0]), "r"(a[1]), "r"(a[2]), "r"(a[3]), "r"(b0), "r"(b1));
}

// ---------------- init: TwS + ITb ----------------
__global__ void init_tables_kernel() {
    const int idx = blockIdx.x * blockDim.x + threadIdx.x;
    const float w = 2.0f * CUDART_PI_F / (float)DD;

    if (idx < TWROWS * (DD / 2)) {
        int c = idx / (DD / 2), op = idx % (DD / 2);
        float v0 = 0.0f, v1 = 0.0f;
        if (c < 2 * FF) {
            int f = (c < FF) ? c : (c - FF);
            int r0 = (f * (2 * op)) % DD, r1 = (f * (2 * op + 1)) % DD;
            if (c < FF) { v0 = cosf(w * (float)r0);  v1 = cosf(w * (float)r1); }
            else        { v0 = -sinf(w * (float)r0); v1 = -sinf(w * (float)r1); }
        }
        uint32_t lp, hp = packsplit_b(v0, v1, lp);
        uint32_t* row = (uint32_t*)(d_TwS + (size_t)c * K3);
        row[op] = hp; row[DD / 2 + op] = lp; row[DD + op] = hp;     // (hi, lo, hi)
    }
    if (idx < DD * (KB5 / 2)) {
        int d = idx / (KB5 / 2), fp = idx % (KB5 / 2);
        float v0 = 0.0f, v1 = 0.0f;
        if (fp < FF) {
            int f = fp;
            bool edge = (f == 0) || (f == DD / 2);
            float c = edge ? (1.0f / DD) : (2.0f / DD);
            int r = (f * d) % DD;
            float ang = w * (float)r;
            v0 = c * cosf(ang);
            v1 = edge ? 0.0f : -c * sinf(ang);
        }
        uint32_t* row = (uint32_t*)(d_ITb + (size_t)d * KB5);
        row[fp] = packh(__float2half(v0), __float2half(v1));
    }
}

// ---------------- W^T split (fold B, bf16 3-term) ----------------
__global__ void splitW_kernel(const float* __restrict__ Wk, const float* __restrict__ Wv,
                              const float* __restrict__ Wq) {
    int idx = blockIdx.x * blockDim.x + threadIdx.x;
    if (idx >= 3 * (DD / 2) * DD) return;
    int z = idx / ((DD / 2) * DD);
    int rem = idx % ((DD / 2) * DD);
    int op = rem / DD, in = rem % DD;
    const float* W = (z == 0) ? Wk : (z == 1) ? Wv : Wq;
    float v0 = W[(size_t)(2 * op) * DD + in];
    float v1 = W[(size_t)(2 * op + 1) * DD + in];
    uint32_t lp, hp = packsplit_b(v0, v1, lp);
    uint32_t* row = (uint32_t*)(d_Ws + (size_t)(z * DD + in) * K3);
    row[op] = hp; row[DD / 2 + op] = hp; row[DD + op] = lp;         // (hi, hi, lo)
}

// ---------------- X convert (stage-3 B, fp16 hi only) ----------------
__global__ void split_X_kernel(const float* __restrict__ x) {
    int idx = blockIdx.x * blockDim.x + threadIdx.x;
    if (idx >= RR * DD / 2) return;
    int r = idx / (DD / 2), cp = idx % (DD / 2);
    float2 v = *(const float2*)&x[(size_t)r * DD + cp * 2];
    ((uint32_t*)(d_Xs + (size_t)r * KB3))[cp] = packh(__float2half(v.x), __float2half(v.y));
}

// ---------------- HMMA GEMM: C[m,n] = sum_k A[m,k]*B[n,k] ----------------
// CTA tile 128xNT, 8 warps (2m x 4n), warp tile 64x(NT/4), BK=64.
// NST-stage cp.async pipeline, single barrier per chunk.
// MODE 0: fp32 C.  MODE 1: C = resid + gain[0]*4096*acc.
// MODE 2 (fold, bf16): fp16-split store into d_Gs (+z slot), masked col<SLOT.
template <int MODE, int NT, int NST, int MINB>
__global__ __launch_bounds__(256, MINB) void hmma_gemm(
    int NKT, int BPER,
    const __nv_bfloat16* __restrict__ A, int lda,
    const __nv_bfloat16* __restrict__ B, int ldb,
    float* __restrict__ C, int ldc,
    const float* __restrict__ resid, const float* __restrict__ gain)
{
    constexpr int NFR = NT / 32;                 // n-frags per warp
    constexpr uint32_t ASZ = 16384u;
    constexpr uint32_t BSZ = (uint32_t)NT * 128u;
    constexpr uint32_t STG = ASZ + BSZ;

    extern __shared__ char smraw[];
    const uint32_t sbase = (s2u(smraw) + 1023u) & ~1023u;
    const int t = threadIdx.x;
    const int lane = t & 31, w = t >> 5;
    const int wm = w >> 2, wn = w & 3;
    const int m0 = blockIdx.x * 128, n0 = blockIdx.y * NT;
    if (MODE == 2) B += (size_t)blockIdx.z * DD * ldb;

    float acc[4][NFR][4];
#pragma unroll
    for (int i = 0; i < 4; i++)
#pragma unroll
        for (int j = 0; j < NFR; j++)
#pragma unroll
            for (int q = 0; q < 4; q++) acc[i][j][q] = 0.0f;

    const int arow = wm * 64 + (lane & 15);
    const int akoff = (lane >> 4) * 16;
    const int brow0 = (lane & 7) + ((lane >> 4) * 8);
    const int bkoff = ((lane >> 3) & 1) * 16;

    auto issue = [&](int kt) {
        const uint32_t sA = sbase + (uint32_t)(kt % NST) * STG;
        const uint32_t sB = sA + ASZ;
        const int bkt = kt % BPER;
#pragma unroll
        for (int i = 0; i < 4; i++) {
            const int s = t + i * 256, row = s >> 3, c = s & 7;
            CP16(sA + swz((uint32_t)(row * 128 + c * 16)),
                 (const char*)A + ((size_t)(m0 + row) * lda + kt * 64 + c * 8) * 2);
        }
#pragma unroll
        for (int i = 0; i < NT / 32; i++) {
            const int s = t + i * 256, row = s >> 3, c = s & 7;
            CP16(sB + swz((uint32_t)(row * 128 + c * 16)),
                 (const char*)B + ((size_t)(n0 + row) * ldb + bkt * 64 + c * 8) * 2);
        }
        CP_COMMIT();
    };

#pragma unroll
    for (int i = 0; i < NST - 1; i++)
        if (i < NKT) issue(i);

    for (int kt = 0; kt < NKT; kt++) {
        const int ahead = NKT - kt - 1 < NST - 2 ? NKT - kt - 1 : NST - 2;
        if (ahead >= 2)      { WG(2); }
        else if (ahead == 1) { WG(1); }
        else                 { WG(0); }
        __syncthreads();
        if (kt + NST - 1 < NKT) issue(kt + NST - 1);

        const uint32_t sA = sbase + (uint32_t)(kt % NST) * STG;
        const uint32_t sB = sA + ASZ;
#pragma unroll
        for (int k16 = 0; k16 < 4; k16++) {
            uint32_t a[4][4];
#pragma unroll
            for (int mf = 0; mf < 4; mf++) {
                uint32_t addr = sA + swz((uint32_t)((arow + mf * 16) * 128 + k16 * 32 + akoff));
                asm volatile("ldmatrix.sync.aligned.m8n8.x4.shared.b16 {%0,%1,%2,%3}, [%4];"
                    : "=r"(a[mf][0]), "=r"(a[mf][1]), "=r"(a[mf][2]), "=r"(a[mf][3]) : "r"(addr));
            }
#pragma unroll
            for (int p = 0; p < NT / 64; p++) {
                uint32_t q0, q1, q2, q3;
                uint32_t addr = sB + swz((uint32_t)((wn * (NT / 4) + p * 16 + brow0) * 128 + k16 * 32 + bkoff));
                asm volatile("ldmatrix.sync.aligned.m8n8.x4.shared.b16 {%0,%1,%2,%3}, [%4];"
                    : "=r"(q0), "=r"(q1), "=r"(q2), "=r"(q3) : "r"(addr));
#pragma unroll
                for (int mf = 0; mf < 4; mf++) {
                    mma16816<MODE == 2>(acc[mf][2 * p], a[mf], q0, q1);
                    mma16816<MODE == 2>(acc[mf][2 * p + 1], a[mf], q2, q3);
                }
            }
        }
    }

    // ---------------- epilogue ----------------
    const int r = lane >> 2, c2 = (lane & 3) * 2;
    if (MODE == 2) {
        __half* gbase = d_Gs + (size_t)blockIdx.z * SLOT * KA3;
#pragma unroll
        for (int mf = 0; mf < 4; mf++) {
#pragma unroll
            for (int nf = 0; nf < NFR; nf++) {
                const int ml = m0 + wm * 64 + mf * 16 + r;
                const int n = n0 + wn * (NT / 4) + nf * 8 + c2;
#pragma unroll
                for (int hh = 0; hh < 2; hh++) {
                    const int mrow = ml + hh * 8;
                    if (mrow < SLOT) {
                        uint32_t lp, hp = packsplit_h(acc[mf][nf][2 * hh], acc[mf][nf][2 * hh + 1], lp);
                        uint32_t* orow = (uint32_t*)(gbase + (size_t)mrow * KA3);
                        orow[n / 2] = hp; orow[KB3 / 2 + n / 2] = lp;   // (hi | lo)
                    }
                }
            }
        }
        return;
    }
    const float g = (MODE == 1) ? gain[0] * ISCALE5 : 0.0f;
#pragma unroll
    for (int mf = 0; mf < 4; mf++) {
#pragma unroll
        for (int nf = 0; nf < NFR; nf++) {
            const int m = m0 + wm * 64 + mf * 16 + r;
            const int n = n0 + wn * (NT / 4) + nf * 8 + c2;
            const size_t o0 = (size_t)m * ldc + n;
            const size_t o1 = (size_t)(m + 8) * ldc + n;
            if (MODE == 1) {
                float2 x0 = *(const float2*)&resid[o0];
                float2 x1 = *(const float2*)&resid[o1];
                *(float2*)&C[o0] = make_float2(x0.x + g * acc[mf][nf][0], x0.y + g * acc[mf][nf][1]);
                *(float2*)&C[o1] = make_float2(x1.x + g * acc[mf][nf][2], x1.y + g * acc[mf][nf][3]);
            } else {
                *(float2*)&C[o0] = make_float2(acc[mf][nf][0], acc[mf][nf][1]);
                *(float2*)&C[o1] = make_float2(acc[mf][nf][2], acc[mf][nf][3]);
            }
        }
    }
}

// ---------------- causal scan (shuffle-based), fused fp16-split + 2^-12 prescale ----------------
__global__ __launch_bounds__(512) void scan_kernel() {
    const int f = blockIdx.x;
    const int b = blockIdx.y;
    const int base = b * SS;
    const int t = threadIdx.x;
    const int lane = t & 31, wid = t >> 5;
    const int s0 = t * 8;

    const float* kre = d_XFt + (size_t)(0 * SLOT + f)      * RR + base;
    const float* kim = d_XFt + (size_t)(0 * SLOT + FF + f) * RR + base;
    const float* vre = d_XFt + (size_t)(1 * SLOT + f)      * RR + base;
    const float* vim = d_XFt + (size_t)(1 * SLOT + FF + f) * RR + base;
    const float* qre = d_XFt + (size_t)(2 * SLOT + f)      * RR + base;
    const float* qim = d_XFt + (size_t)(2 * SLOT + FF + f) * RR + base;

    float kr[8], ki[8], vr[8], vi[8], qr[8], qi[8];
#pragma unroll
    for (int h = 0; h < 2; h++) {
        *(float4*)(kr + 4 * h) = *(const float4*)(kre + s0 + 4 * h);
        *(float4*)(ki + 4 * h) = *(const float4*)(kim + s0 + 4 * h);
        *(float4*)(vr + 4 * h) = *(const float4*)(vre + s0 + 4 * h);
        *(float4*)(vi + 4 * h) = *(const float4*)(vim + s0 + 4 * h);
        *(float4*)(qr + 4 * h) = *(const float4*)(qre + s0 + 4 * h);
        *(float4*)(qi + 4 * h) = *(const float4*)(qim + s0 + 4 * h);
    }

    float lr[8], li[8], runr = 0.0f, runi = 0.0f;
#pragma unroll
    for (int i = 0; i < 8; i++) {
        float zr = kr[i] * vr[i] - ki[i] * vi[i];
        float zi = kr[i] * vi[i] + ki[i] * vr[i];
        runr += zr; runi += zi;
        lr[i] = runr; li[i] = runi;
    }

    float wr = runr, wi = runi;
#pragma unroll
    for (int off = 1; off < 32; off <<= 1) {
        float pr = __shfl_up_sync(0xFFFFFFFFu, wr, off);
        float pi = __shfl_up_sync(0xFFFFFFFFu, wi, off);
        if (lane >= off) { wr += pr; wi += pi; }
    }
    __shared__ float swr[16], swi[16];
    if (lane == 31) { swr[wid] = wr; swi[wid] = wi; }
    __syncthreads();
    if (t < 32) {
        float vr2 = (t < 16) ? swr[t] : 0.0f;
        float vi2 = (t < 16) ? swi[t] : 0.0f;
#pragma unroll
        for (int off = 1; off < 16; off <<= 1) {
            float pr = __shfl_up_sync(0xFFFFFFFFu, vr2, off);
            float pi = __shfl_up_sync(0xFFFFFFFFu, vi2, off);
            if (lane >= off) { vr2 += pr; vi2 += pi; }
        }
        if (t < 16) { swr[t] = vr2; swi[t] = vi2; }
    }
    __syncthreads();
    const float baser = (wid > 0) ? swr[wid - 1] : 0.0f;
    const float basei = (wid > 0) ? swi[wid - 1] : 0.0f;
    const float exr = baser + (wr - runr);
    const float exi = basei + (wi - runi);

#pragma unroll
    for (int i = 0; i < 8; i++) {
        float mr = exr + lr[i];
        float mi = exi + li[i];
        float ox = (mr * qr[i] + mi * qi[i]) * SCALE5;   // Re -> j=2f
        float oy = (mi * qr[i] - mr * qi[i]) * SCALE5;   // Im -> j=2f+1
        uint32_t lp, hp = packsplit_h(ox, oy, lp);
        uint32_t* orow = (uint32_t*)(d_OFs + (size_t)(base + s0 + i) * KA5);
        orow[f] = hp; orow[KB5 / 2 + f] = lp;            // (hi | lo)
    }
}

// ---------------- launch ----------------
#define SMEM_BIG  (3 * (16384 + 128 * 128) + 1024)       // NT=128, 3-stage (2 CTAs/SM)
#define SMEM_FOLD (4 * (16384 + 128 * 128) + 1024)       // NT=128, 4-stage (fold)
extern "C" void kernel_launch(void* const* d_in, const int* in_sizes, int n_in,
                              void* d_out, int out_size) {
    const float* x    = (const float*)d_in[0];
    const float* Wk   = (const float*)d_in[1];
    const float* Wv   = (const float*)d_in[2];
    const float* Wq   = (const float*)d_in[3];
    const float* gain = (const float*)d_in[4];
    float* out = (float*)d_out;

    void *pTwS, *pWs, *pGs, *pXs, *pOFs, *pITb, *pXFt;
    cudaGetSymbolAddress(&pTwS, d_TwS);
    cudaGetSymbolAddress(&pWs,  d_Ws);
    cudaGetSymbolAddress(&pGs,  d_Gs);
    cudaGetSymbolAddress(&pXs,  d_Xs);
    cudaGetSymbolAddress(&pOFs, d_OFs);
    cudaGetSymbolAddress(&pITb, d_ITb);
    cudaGetSymbolAddress(&pXFt, d_XFt);

    cudaFuncSetAttribute((const void*)hmma_gemm<0, 128, 3, 2>, cudaFuncAttributeMaxDynamicSharedMemorySize, SMEM_BIG);
    cudaFuncSetAttribute((const void*)hmma_gemm<1, 128, 3, 2>, cudaFuncAttributeMaxDynamicSharedMemorySize, SMEM_BIG);
    cudaFuncSetAttribute((const void*)hmma_gemm<2, 128, 4, 1>, cudaFuncAttributeMaxDynamicSharedMemorySize, SMEM_FOLD);

    // 0) tables
    init_tables_kernel<<<(TWROWS * (DD / 2) + 255) / 256, 256>>>();

    // 1) W^T split (fold B) + X fp16 convert (stage-3 B)
    splitW_kernel<<<(3 * (DD / 2) * DD + 255) / 256, 256>>>(Wk, Wv, Wq);
    split_X_kernel<<<(RR * DD / 2 + 255) / 256, 256>>>(x);

    // 2) fold GEMM (bf16 3-term, NT=128, 4-stage, fp16-split store into Gs)
    hmma_gemm<2, 128, 4, 1><<<dim3(TWROWS / 128, DD / 128, 3), 256, SMEM_FOLD>>>(
        K3 / 64, K3 / 64,
        (const __nv_bfloat16*)pTwS, K3, (const __nv_bfloat16*)pWs, K3,
        nullptr, 0, nullptr, nullptr);

    // 3) stage-3 GEMM (fp16 2-term, 2 CTAs/SM): XFt[col, r]  M=2432, N=16384, K=1536
    hmma_gemm<0, 128, 3, 2><<<dim3(MROWS / 128, RR / 128), 256, SMEM_BIG>>>(
        KA3 / 64, KB3 / 64,
        (const __nv_bfloat16*)pGs, KA3, (const __nv_bfloat16*)pXs, KB3,
        (float*)pXFt, RR, nullptr, nullptr);

    // 4) causal scan -> OFs (fp16 split + prescale, fused)
    scan_kernel<<<dim3(FF, BB), 512>>>();

    // 5) stage-5 GEMM + residual (fp16 2-term, 2 CTAs/SM): out[r,d]  M=16384, N=768, K=1664
    hmma_gemm<1, 128, 3, 2><<<dim3(RR / 128, DD / 128), 256, SMEM_BIG>>>(
        KA5 / 64, KB5 / 64,
        (const __nv_bfloat16*)pOFs, KA5, (const __nv_bfloat16*)pITb, KB5,
        out, DD, x, gain);
}